// round 2
// baseline (speedup 1.0000x reference)
#include <cuda_runtime.h>
#include <stdint.h>

// Problem constants
#define C_DIM 16
#define G_DIM 8192
#define S_DIM 8
#define L_DIM 3
#define B_DIM 32
#define SL    (S_DIM * L_DIM)   // 24

// xt: x transposed to (G, B) so a gather of one index j for all 32 b's is a
// single contiguous 128B line xt[j*32 .. j*32+31].
__device__ float g_xt[G_DIM * B_DIM];

// 1 if I is stored as int64, 0 if int32. Detected at runtime, deterministic.
__device__ int g_idx_is64;

// ---------------------------------------------------------------------------
// Kernel 0: detect index element width.
// If data is int64 with values in [0, 8192), every high 32-bit word is 0.
// If data is int32, the odd words are random indices; P(all 16 == 0) ~ 0.
// ---------------------------------------------------------------------------
__global__ void detect_idx_width_kernel(const int* __restrict__ Iw) {
    int is64 = 1;
#pragma unroll
    for (int k = 0; k < 16; k++) {
        if (Iw[2 * k + 1] != 0) is64 = 0;
    }
    g_idx_is64 = is64;
}

// ---------------------------------------------------------------------------
// Kernel 1: transpose x (B,G) -> xt (G,B). 256 blocks of (32,32).
// ---------------------------------------------------------------------------
__global__ void transpose_x_kernel(const float* __restrict__ x) {
    __shared__ float tile[32][33];
    int g_base = blockIdx.x * 32;
    int tx = threadIdx.x;   // g within tile (read) / b (write)
    int ty = threadIdx.y;   // b (read) / g within tile (write)

    tile[ty][tx] = x[ty * G_DIM + g_base + tx];
    __syncthreads();
    g_xt[(g_base + ty) * B_DIM + tx] = tile[tx][ty];
}

// ---------------------------------------------------------------------------
// Kernel 2: one warp per (c,g). lane = b.
//   out[c,b,g] = sum_s prod_l xt[I[c,g,s,l]*32 + b]
// Block: 1024 threads = 32 warps = 32 consecutive g for one c.
// Grid: C * (G/32) = 4096 blocks.
// Writes go through an smem transpose so global stores are 128B-coalesced.
// ---------------------------------------------------------------------------
__global__ __launch_bounds__(1024)
void clause_body_kernel(const void* __restrict__ Iraw,
                        float* __restrict__ out) {
    __shared__ float tile[32][33];

    const int lane = threadIdx.x & 31;
    const int warp = threadIdx.x >> 5;

    const int c      = blockIdx.x >> 8;          // G/32 = 256 tiles per c
    const int g_base = (blockIdx.x & 255) << 5;  // *32
    const int g      = g_base + warp;

    const long long elem = ((long long)(c * G_DIM + g)) * SL;

    // 24 indices for this (c,g): contiguous. Lanes 0..23 each load one.
    int myidx = 0;
    if (lane < SL) {
        if (g_idx_is64) {
            myidx = (int)((const long long*)Iraw)[elem + lane];
        } else {
            myidx = ((const int*)Iraw)[elem + lane];
        }
        myidx &= (G_DIM - 1);   // safety mask; no-op on valid indices
    }

    float acc = 0.0f;
#pragma unroll
    for (int s = 0; s < S_DIM; s++) {
        int i0 = __shfl_sync(0xffffffffu, myidx, s * 3 + 0);
        int i1 = __shfl_sync(0xffffffffu, myidx, s * 3 + 1);
        int i2 = __shfl_sync(0xffffffffu, myidx, s * 3 + 2);
        float v0 = g_xt[i0 * B_DIM + lane];
        float v1 = g_xt[i1 * B_DIM + lane];
        float v2 = g_xt[i2 * B_DIM + lane];
        acc += v0 * v1 * v2;
    }

    // acc holds value for (c, b=lane, g=g_base+warp).
    tile[warp][lane] = acc;
    __syncthreads();

    // warp w writes b = w, g = g_base + lane : contiguous in g.
    float v = tile[lane][warp];
    out[((long long)c * B_DIM + warp) * G_DIM + g_base + lane] = v;
}

extern "C" void kernel_launch(void* const* d_in, const int* in_sizes, int n_in,
                              void* d_out, int out_size) {
    // Identify inputs by element count, independent of metadata order.
    // x: B*G = 262144 elements. I: C*G*S*L = 3145728 elements.
    const float* x = nullptr;
    const void*  I = nullptr;
    for (int i = 0; i < n_in; i++) {
        if (in_sizes[i] == B_DIM * G_DIM)      x = (const float*)d_in[i];
        else if (in_sizes[i] == C_DIM * G_DIM * SL) I = d_in[i];
    }
    float* out = (float*)d_out;

    detect_idx_width_kernel<<<1, 1>>>((const int*)I);

    dim3 tb(32, 32);
    transpose_x_kernel<<<G_DIM / 32, tb>>>(x);

    clause_body_kernel<<<C_DIM * (G_DIM / 32), 1024>>>(I, out);
}

// round 3
// speedup vs baseline: 1.4474x; 1.4474x over previous
#include <cuda_runtime.h>
#include <cuda_fp16.h>
#include <stdint.h>

#define C_DIM 16
#define G_DIM 8192
#define S_DIM 8
#define L_DIM 3
#define B_DIM 32
#define SL    (S_DIM * L_DIM)   // 24

// xt in fp16: (G, 32) halves = (G, 16) half2. Row = 64B, working set 512KB.
__device__ __half2 g_xh[G_DIM * (B_DIM / 2)];
__device__ int g_idx_is64;

// ---------------------------------------------------------------------------
// Kernel 1: transpose x (B,G) f32 -> g_xh (G, B/2) half2.
// Also detects index width (int64 vs int32) in block 0, thread 0.
// 256 blocks of (32,32).
// ---------------------------------------------------------------------------
__global__ void transpose_x_kernel(const float* __restrict__ x,
                                   const int* __restrict__ Iw) {
    __shared__ float tile[32][33];

    if (blockIdx.x == 0 && threadIdx.x == 0 && threadIdx.y == 0) {
        // int64 indices < 8192 => every high word is 0. int32 random indices:
        // P(16 odd words all zero) ~ (1/8192)^16 ~ 0.
        int is64 = 1;
#pragma unroll
        for (int k = 0; k < 16; k++) {
            if (Iw[2 * k + 1] != 0) is64 = 0;
        }
        g_idx_is64 = is64;
    }

    int g_base = blockIdx.x * 32;
    int tx = threadIdx.x;   // g within tile
    int ty = threadIdx.y;   // b

    tile[ty][tx] = x[ty * G_DIM + g_base + tx];
    __syncthreads();

    int t = ty * 32 + tx;
    if (t < 512) {
        int i = t >> 4;       // g within tile
        int j = t & 15;       // b-pair
        g_xh[(g_base + i) * (B_DIM / 2) + j] =
            __floats2half2_rn(tile[2 * j][i], tile[2 * j + 1][i]);
    }
}

// ---------------------------------------------------------------------------
// Kernel 2: block = 64 g for one c. Warp handles 2 g (half-warp each).
// lane&15 = b-pair (half2). Indices staged in smem (broadcast LDS, no shfl).
// Gather: half-warp reads one 64B row per index (2 lines per LDG warp-instr).
// Output transposed in smem for coalesced stores.
// Grid: C * G/64 = 2048 blocks of 1024 threads.
// ---------------------------------------------------------------------------
__global__ __launch_bounds__(1024)
void clause_body_kernel(const void* __restrict__ Iraw,
                        float* __restrict__ out) {
    __shared__ int   sIdx[64 * SL];     // 6 KB
    __shared__ float tile[64][33];      // 8.25 KB

    const int tid    = threadIdx.x;
    const int c      = blockIdx.x >> 7;          // 128 tiles per c
    const int g_base = (blockIdx.x & 127) << 6;  // *64

    // Stage 64*24 indices into smem as int32, masked for safety.
    const long long base = ((long long)(c * G_DIM + g_base)) * SL;
    if (g_idx_is64) {
        const long long* Ip = (const long long*)Iraw + base;
        for (int k = tid; k < 64 * SL; k += 1024)
            sIdx[k] = ((int)Ip[k]) & (G_DIM - 1);
    } else {
        const int* Ip = (const int*)Iraw + base;
        for (int k = tid; k < 64 * SL; k += 1024)
            sIdx[k] = Ip[k] & (G_DIM - 1);
    }
    __syncthreads();

    const int warp = tid >> 5;
    const int lane = tid & 31;
    const int gl   = 2 * warp + (lane >> 4);   // local g (0..63)
    const int p    = lane & 15;                // b-pair

    const int* myIdx = &sIdx[gl * SL];

    float accx = 0.0f, accy = 0.0f;
#pragma unroll
    for (int s = 0; s < S_DIM; s++) {
        int j0 = myIdx[3 * s + 0];
        int j1 = myIdx[3 * s + 1];
        int j2 = myIdx[3 * s + 2];
        float2 v0 = __half22float2(g_xh[j0 * (B_DIM / 2) + p]);
        float2 v1 = __half22float2(g_xh[j1 * (B_DIM / 2) + p]);
        float2 v2 = __half22float2(g_xh[j2 * (B_DIM / 2) + p]);
        accx += v0.x * v1.x * v2.x;
        accy += v0.y * v1.y * v2.y;
    }

    // acc{x,y} = out[c, b=2p / 2p+1, g_base+gl]
    tile[gl][2 * p]     = accx;
    tile[gl][2 * p + 1] = accy;
    __syncthreads();

    // Coalesced writeout: 2048 elements, 2 per thread.
#pragma unroll
    for (int k = 0; k < 2; k++) {
        int e  = tid + k * 1024;
        int b  = e >> 6;     // 0..31
        int gg = e & 63;
        out[((long long)c * B_DIM + b) * G_DIM + g_base + gg] = tile[gg][b];
    }
}

extern "C" void kernel_launch(void* const* d_in, const int* in_sizes, int n_in,
                              void* d_out, int out_size) {
    // Identify inputs by element count (order-independent).
    const float* x = nullptr;
    const void*  I = nullptr;
    for (int i = 0; i < n_in; i++) {
        if (in_sizes[i] == B_DIM * G_DIM)            x = (const float*)d_in[i];
        else if (in_sizes[i] == C_DIM * G_DIM * SL)  I = d_in[i];
    }
    float* out = (float*)d_out;

    dim3 tb(32, 32);
    transpose_x_kernel<<<G_DIM / 32, tb>>>(x, (const int*)I);

    clause_body_kernel<<<C_DIM * (G_DIM / 64), 1024>>>(I, out);
}

// round 4
// speedup vs baseline: 1.4491x; 1.0012x over previous
#include <cuda_runtime.h>
#include <cuda_fp16.h>
#include <stdint.h>

#define C_DIM 16
#define G_DIM 8192
#define S_DIM 8
#define L_DIM 3
#define B_DIM 32
#define SL    (S_DIM * L_DIM)   // 24

// xt in fp16: row g = 32 halves = 64B. Working set 512KB (L2-resident, ~44% L1 hit).
__device__ __half2 g_xh[G_DIM * (B_DIM / 2)];
__device__ int g_idx_is64;

// ---------------------------------------------------------------------------
// Kernel 1: transpose x (B,G) f32 -> g_xh (G, B/2) half2. Detects idx width.
// ---------------------------------------------------------------------------
__global__ void transpose_x_kernel(const float* __restrict__ x,
                                   const int* __restrict__ Iw) {
    __shared__ float tile[32][33];

    if (blockIdx.x == 0 && threadIdx.x == 0 && threadIdx.y == 0) {
        int is64 = 1;
#pragma unroll
        for (int k = 0; k < 16; k++) {
            if (Iw[2 * k + 1] != 0) is64 = 0;
        }
        g_idx_is64 = is64;
    }

    int g_base = blockIdx.x * 32;
    int tx = threadIdx.x;   // g within tile
    int ty = threadIdx.y;   // b

    tile[ty][tx] = x[ty * G_DIM + g_base + tx];
    __syncthreads();

    int t = ty * 32 + tx;
    if (t < 512) {
        int i = t >> 4;       // g within tile
        int j = t & 15;       // b-pair
        g_xh[(g_base + i) * (B_DIM / 2) + j] =
            __floats2half2_rn(tile[2 * j][i], tile[2 * j + 1][i]);
    }
}

// ---------------------------------------------------------------------------
// Kernel 2: block = 128 g for one c. Warp handles 4 g; lane>>3 = sub-g,
// lane&7 = byte-octet of the 64B row (LDG.64 = 4 halves per lane).
// Indices staged in smem pre-scaled to byte offsets (idx*64).
// Products in half2 (HMUL2), accumulate in fp32. smem transpose for stores.
// Grid: C * G/128 = 1024 blocks of 1024 threads.
// ---------------------------------------------------------------------------
__global__ __launch_bounds__(1024)
void clause_body_kernel(const void* __restrict__ Iraw,
                        float* __restrict__ out) {
    __shared__ int   sIdx[128 * SL];    // 12 KB, holds idx*64 (byte offsets)
    __shared__ float tile[128][33];     // 16.5 KB

    const int tid    = threadIdx.x;
    const int c      = blockIdx.x >> 6;          // 64 tiles of 128 g per c
    const int g_base = (blockIdx.x & 63) << 7;   // *128

    // Stage 128*24 = 3072 indices, pre-scaled by 64 (row byte stride).
    const long long base = ((long long)(c * G_DIM + g_base)) * SL;
    if (g_idx_is64) {
        const long long* Ip = (const long long*)Iraw + base;
#pragma unroll
        for (int k = 0; k < 3; k++) {
            int e = tid + k * 1024;
            sIdx[e] = (((int)Ip[e]) & (G_DIM - 1)) << 6;
        }
    } else {
        const int* Ip = (const int*)Iraw + base;
#pragma unroll
        for (int k = 0; k < 3; k++) {
            int e = tid + k * 1024;
            sIdx[e] = (Ip[e] & (G_DIM - 1)) << 6;
        }
    }
    __syncthreads();

    const int warp = tid >> 5;
    const int lane = tid & 31;
    const int gl   = 4 * warp + (lane >> 3);   // local g (0..127)
    const int oct  = lane & 7;                 // which 8B of the 64B row

    const char* xb = (const char*)g_xh + oct * 8;
    const int* myIdx = &sIdx[gl * SL];

    float a0 = 0.f, a1 = 0.f, a2 = 0.f, a3 = 0.f;
#pragma unroll
    for (int s = 0; s < S_DIM; s++) {
        int j0 = myIdx[3 * s + 0];
        int j1 = myIdx[3 * s + 1];
        int j2 = myIdx[3 * s + 2];
        uint2 r0 = *(const uint2*)(xb + j0);
        uint2 r1 = *(const uint2*)(xb + j1);
        uint2 r2 = *(const uint2*)(xb + j2);
        __half2 v0a = *(__half2*)&r0.x, v0b = *(__half2*)&r0.y;
        __half2 v1a = *(__half2*)&r1.x, v1b = *(__half2*)&r1.y;
        __half2 v2a = *(__half2*)&r2.x, v2b = *(__half2*)&r2.y;
        __half2 ta = __hmul2(__hmul2(v0a, v1a), v2a);
        __half2 tb = __hmul2(__hmul2(v0b, v1b), v2b);
        float2 fa = __half22float2(ta);
        float2 fb = __half22float2(tb);
        a0 += fa.x; a1 += fa.y;
        a2 += fb.x; a3 += fb.y;
    }

    // Thread holds b = 4*oct .. 4*oct+3 for g = g_base+gl.
    tile[gl][4 * oct + 0] = a0;
    tile[gl][4 * oct + 1] = a1;
    tile[gl][4 * oct + 2] = a2;
    tile[gl][4 * oct + 3] = a3;
    __syncthreads();

    // Coalesced writeout: 4096 elements, 4 per thread. Consecutive tid -> g.
#pragma unroll
    for (int k = 0; k < 4; k++) {
        int e  = tid + k * 1024;
        int b  = e >> 7;     // 0..31
        int gg = e & 127;
        out[((long long)c * B_DIM + b) * G_DIM + g_base + gg] = tile[gg][b];
    }
}

extern "C" void kernel_launch(void* const* d_in, const int* in_sizes, int n_in,
                              void* d_out, int out_size) {
    const float* x = nullptr;
    const void*  I = nullptr;
    for (int i = 0; i < n_in; i++) {
        if (in_sizes[i] == B_DIM * G_DIM)            x = (const float*)d_in[i];
        else if (in_sizes[i] == C_DIM * G_DIM * SL)  I = d_in[i];
    }
    float* out = (float*)d_out;

    dim3 tb(32, 32);
    transpose_x_kernel<<<G_DIM / 32, tb>>>(x, (const int*)I);

    clause_body_kernel<<<C_DIM * (G_DIM / 128), 1024>>>(I, out);
}

// round 5
// speedup vs baseline: 1.5644x; 1.0795x over previous
#include <cuda_runtime.h>
#include <cuda_fp16.h>
#include <stdint.h>

#define C_DIM 16
#define G_DIM 8192
#define S_DIM 8
#define L_DIM 3
#define B_DIM 32
#define SL    (S_DIM * L_DIM)   // 24

#define G_PER_BLOCK 64
#define IDX_STRIDE  26          // padded index row: conflict-free LDS banks
#define TILE_STRIDE 65          // tile[b][g] row stride: conflict-free STS/LDS

// xt in fp16: row g = 32 halves = 64B, 64B-aligned. Working set 512KB.
__device__ __align__(128) __half2 g_xh[G_DIM * (B_DIM / 2)];
__device__ int g_idx_is64;

// ---------------------------------------------------------------------------
// Kernel 1: transpose x (B,G) f32 -> g_xh (G, B/2) half2. Detects idx width.
// ---------------------------------------------------------------------------
__global__ void transpose_x_kernel(const float* __restrict__ x,
                                   const int* __restrict__ Iw) {
    __shared__ float tile[32][33];

    if (blockIdx.x == 0 && threadIdx.x == 0 && threadIdx.y == 0) {
        int is64 = 1;
#pragma unroll
        for (int k = 0; k < 16; k++) {
            if (Iw[2 * k + 1] != 0) is64 = 0;
        }
        g_idx_is64 = is64;
    }

    int g_base = blockIdx.x * 32;
    int tx = threadIdx.x;   // g within tile
    int ty = threadIdx.y;   // b

    tile[ty][tx] = x[ty * G_DIM + g_base + tx];
    __syncthreads();

    int t = ty * 32 + tx;
    if (t < 512) {
        int i = t >> 4;       // g within tile
        int j = t & 15;       // b-pair
        g_xh[(g_base + i) * (B_DIM / 2) + j] =
            __floats2half2_rn(tile[2 * j][i], tile[2 * j + 1][i]);
    }
}

// ---------------------------------------------------------------------------
// Kernel 2: block = 256 threads = 8 warps; warp handles 8 g (lane>>2 = sub-g,
// lane&3 = 16B quarter of the 64B row; LDG.128 per gather).
// Indices in smem pre-scaled to byte offsets, padded stride (no conflicts).
// Products in half2, accumulate fp32. Output tile [b][g] for coalesced stores.
// Grid: C * G/64 = 2048 blocks.
// ---------------------------------------------------------------------------
__global__ __launch_bounds__(256, 6)
void clause_body_kernel(const void* __restrict__ Iraw,
                        float* __restrict__ out) {
    __shared__ int   sIdx[G_PER_BLOCK * IDX_STRIDE];   // 6.5 KB
    __shared__ float tile[B_DIM][TILE_STRIDE];         // 8.3 KB

    const int tid    = threadIdx.x;
    const int c      = blockIdx.x >> 7;          // 128 tiles of 64 g per c
    const int g_base = (blockIdx.x & 127) << 6;  // *64

    // Stage 64*24 = 1536 indices (padded rows), pre-scaled by 64.
    const long long base = ((long long)(c * G_DIM + g_base)) * SL;
    if (g_idx_is64) {
        const long long* Ip = (const long long*)Iraw + base;
#pragma unroll
        for (int k = 0; k < 6; k++) {
            int e = tid + k * 256;
            int gg = e / SL, kk = e - gg * SL;
            sIdx[gg * IDX_STRIDE + kk] = (((int)Ip[e]) & (G_DIM - 1)) << 6;
        }
    } else {
        const int* Ip = (const int*)Iraw + base;
#pragma unroll
        for (int k = 0; k < 6; k++) {
            int e = tid + k * 256;
            int gg = e / SL, kk = e - gg * SL;
            sIdx[gg * IDX_STRIDE + kk] = (Ip[e] & (G_DIM - 1)) << 6;
        }
    }
    __syncthreads();

    const int warp = tid >> 5;
    const int lane = tid & 31;
    const int gl   = warp * 8 + (lane >> 2);   // local g (0..63)
    const int q    = lane & 3;                 // 16B quarter -> b = 8q..8q+7

    const char* xb = (const char*)g_xh + q * 16;
    const int* myIdx = &sIdx[gl * IDX_STRIDE];

    float a0 = 0.f, a1 = 0.f, a2 = 0.f, a3 = 0.f;
    float a4 = 0.f, a5 = 0.f, a6 = 0.f, a7 = 0.f;
#pragma unroll
    for (int s = 0; s < S_DIM; s++) {
        int j0 = myIdx[3 * s + 0];
        int j1 = myIdx[3 * s + 1];
        int j2 = myIdx[3 * s + 2];
        uint4 r0 = *(const uint4*)(xb + j0);
        uint4 r1 = *(const uint4*)(xb + j1);
        uint4 r2 = *(const uint4*)(xb + j2);
        __half2 t0 = __hmul2(__hmul2(*(__half2*)&r0.x, *(__half2*)&r1.x), *(__half2*)&r2.x);
        __half2 t1 = __hmul2(__hmul2(*(__half2*)&r0.y, *(__half2*)&r1.y), *(__half2*)&r2.y);
        __half2 t2 = __hmul2(__hmul2(*(__half2*)&r0.z, *(__half2*)&r1.z), *(__half2*)&r2.z);
        __half2 t3 = __hmul2(__hmul2(*(__half2*)&r0.w, *(__half2*)&r1.w), *(__half2*)&r2.w);
        float2 f0 = __half22float2(t0);
        float2 f1 = __half22float2(t1);
        float2 f2 = __half22float2(t2);
        float2 f3 = __half22float2(t3);
        a0 += f0.x; a1 += f0.y; a2 += f1.x; a3 += f1.y;
        a4 += f2.x; a5 += f2.y; a6 += f3.x; a7 += f3.y;
    }

    // Thread holds b = 8q .. 8q+7 for g = g_base+gl. Write tile[b][gl].
    // Banks: (8q+i)*65 + gl mod 32 == (8q + i + 8w + sg) — all distinct per i.
    tile[8 * q + 0][gl] = a0;
    tile[8 * q + 1][gl] = a1;
    tile[8 * q + 2][gl] = a2;
    tile[8 * q + 3][gl] = a3;
    tile[8 * q + 4][gl] = a4;
    tile[8 * q + 5][gl] = a5;
    tile[8 * q + 6][gl] = a6;
    tile[8 * q + 7][gl] = a7;
    __syncthreads();

    // Coalesced writeout: 2048 elements, 8 per thread; warp = 32 consecutive g.
#pragma unroll
    for (int k = 0; k < 8; k++) {
        int e  = tid + k * 256;
        int b  = e >> 6;     // 0..31
        int gg = e & 63;
        out[((long long)c * B_DIM + b) * G_DIM + g_base + gg] = tile[b][gg];
    }
}

extern "C" void kernel_launch(void* const* d_in, const int* in_sizes, int n_in,
                              void* d_out, int out_size) {
    const float* x = nullptr;
    const void*  I = nullptr;
    for (int i = 0; i < n_in; i++) {
        if (in_sizes[i] == B_DIM * G_DIM)            x = (const float*)d_in[i];
        else if (in_sizes[i] == C_DIM * G_DIM * SL)  I = d_in[i];
    }
    float* out = (float*)d_out;

    dim3 tb(32, 32);
    transpose_x_kernel<<<G_DIM / 32, tb>>>(x, (const int*)I);

    clause_body_kernel<<<C_DIM * (G_DIM / G_PER_BLOCK), 256>>>(I, out);
}

// round 6
// speedup vs baseline: 1.7208x; 1.1000x over previous
#include <cuda_runtime.h>
#include <cuda_fp16.h>
#include <stdint.h>

#define C_DIM 16
#define G_DIM 8192
#define S_DIM 8
#define L_DIM 3
#define B_DIM 32
#define SL    (S_DIM * L_DIM)   // 24

#define G_PER_BLOCK 32
#define IDX_STRIDE  26          // padded index row: conflict-free LDS banks

// xt in fp16: row g = 32 halves = 64B, aligned. Working set 512KB.
__device__ __align__(128) __half2 g_xh[G_DIM * (B_DIM / 2)];
__device__ int g_idx_is64;

// ---------------------------------------------------------------------------
// Kernel 1: transpose x (B,G) f32 -> g_xh (G, B/2) half2. Detects idx width.
// ---------------------------------------------------------------------------
__global__ void transpose_x_kernel(const float* __restrict__ x,
                                   const int* __restrict__ Iw) {
    __shared__ float tile[32][33];

    if (blockIdx.x == 0 && threadIdx.x == 0 && threadIdx.y == 0) {
        int is64 = 1;
#pragma unroll
        for (int k = 0; k < 16; k++) {
            if (Iw[2 * k + 1] != 0) is64 = 0;
        }
        g_idx_is64 = is64;
    }

    int g_base = blockIdx.x * 32;
    int tx = threadIdx.x;   // g within tile
    int ty = threadIdx.y;   // b

    tile[ty][tx] = x[ty * G_DIM + g_base + tx];
    __syncthreads();

    int t = ty * 32 + tx;
    if (t < 512) {
        int i = t >> 4;       // g within tile
        int j = t & 15;       // b-pair
        g_xh[(g_base + i) * (B_DIM / 2) + j] =
            __floats2half2_rn(tile[2 * j][i], tile[2 * j + 1][i]);
    }
}

// ---------------------------------------------------------------------------
// Kernel 2: block = 256 threads = 8 warps = 32 g. Warp handles 4 g
// (lane>>3 = sub-g, lane&7 = 8B octet of the 64B row; LDG.64 per gather).
// 4 b per thread -> 4 fp32 accumulators, ~30 regs -> 8 blocks/SM (64 warps).
// Indices in smem pre-scaled to byte offsets, padded stride (conflict-free).
// Grid: C * G/32 = 4096 blocks.
// ---------------------------------------------------------------------------
__global__ __launch_bounds__(256, 8)
void clause_body_kernel(const void* __restrict__ Iraw,
                        float* __restrict__ out) {
    __shared__ int   sIdx[G_PER_BLOCK * IDX_STRIDE];   // 3.3 KB
    __shared__ float tile[B_DIM][33];                  // 4.2 KB

    const int tid    = threadIdx.x;
    const int c      = blockIdx.x >> 8;           // 256 tiles of 32 g per c
    const int g_base = (blockIdx.x & 255) << 5;   // *32

    // Stage 32*24 = 768 indices, pre-scaled by 64 (row byte stride).
    const long long base = ((long long)(c * G_DIM + g_base)) * SL;
    if (g_idx_is64) {
        const long long* Ip = (const long long*)Iraw + base;
#pragma unroll
        for (int k = 0; k < 3; k++) {
            int e = tid + k * 256;
            int gg = e / SL, kk = e - gg * SL;
            sIdx[gg * IDX_STRIDE + kk] = (((int)Ip[e]) & (G_DIM - 1)) << 6;
        }
    } else {
        const int* Ip = (const int*)Iraw + base;
#pragma unroll
        for (int k = 0; k < 3; k++) {
            int e = tid + k * 256;
            int gg = e / SL, kk = e - gg * SL;
            sIdx[gg * IDX_STRIDE + kk] = (Ip[e] & (G_DIM - 1)) << 6;
        }
    }
    __syncthreads();

    const int warp = tid >> 5;
    const int lane = tid & 31;
    const int gl   = warp * 4 + (lane >> 3);   // local g (0..31)
    const int oct  = lane & 7;                 // 8B octet -> b = 4*oct..4*oct+3

    const char* xb = (const char*)g_xh + oct * 8;
    const int* myIdx = &sIdx[gl * IDX_STRIDE];

    float a0 = 0.f, a1 = 0.f, a2 = 0.f, a3 = 0.f;
#pragma unroll
    for (int s = 0; s < S_DIM; s++) {
        int j0 = myIdx[3 * s + 0];
        int j1 = myIdx[3 * s + 1];
        int j2 = myIdx[3 * s + 2];
        uint2 r0 = *(const uint2*)(xb + j0);
        uint2 r1 = *(const uint2*)(xb + j1);
        uint2 r2 = *(const uint2*)(xb + j2);
        __half2 t0 = __hmul2(__hmul2(*(__half2*)&r0.x, *(__half2*)&r1.x), *(__half2*)&r2.x);
        __half2 t1 = __hmul2(__hmul2(*(__half2*)&r0.y, *(__half2*)&r1.y), *(__half2*)&r2.y);
        float2 f0 = __half22float2(t0);
        float2 f1 = __half22float2(t1);
        a0 += f0.x; a1 += f0.y;
        a2 += f1.x; a3 += f1.y;
    }

    // Thread holds b = 4*oct .. 4*oct+3 for g = g_base+gl. tile[b][gl]:
    // bank = (4*oct+i)*33 + gl mod 32 = 4*oct + gl + i  -> conflict-free.
    tile[4 * oct + 0][gl] = a0;
    tile[4 * oct + 1][gl] = a1;
    tile[4 * oct + 2][gl] = a2;
    tile[4 * oct + 3][gl] = a3;
    __syncthreads();

    // Coalesced writeout: 1024 elements, 4 per thread; warp = 32 consecutive g.
#pragma unroll
    for (int k = 0; k < 4; k++) {
        int e  = tid + k * 256;
        int b  = e >> 5;     // 0..31
        int gg = e & 31;
        out[((long long)c * B_DIM + b) * G_DIM + g_base + gg] = tile[b][gg];
    }
}

extern "C" void kernel_launch(void* const* d_in, const int* in_sizes, int n_in,
                              void* d_out, int out_size) {
    const float* x = nullptr;
    const void*  I = nullptr;
    for (int i = 0; i < n_in; i++) {
        if (in_sizes[i] == B_DIM * G_DIM)            x = (const float*)d_in[i];
        else if (in_sizes[i] == C_DIM * G_DIM * SL)  I = d_in[i];
    }
    float* out = (float*)d_out;

    dim3 tb(32, 32);
    transpose_x_kernel<<<G_DIM / 32, tb>>>(x, (const int*)I);

    clause_body_kernel<<<C_DIM * (G_DIM / G_PER_BLOCK), 256>>>(I, out);
}